// round 15
// baseline (speedup 1.0000x reference)
#include <cuda_runtime.h>
#include <mma.h>
#include <cuda_fp16.h>
#include <cstdint>

using namespace nvcuda;

// Problem constants
#define B_     2
#define T_     1024
#define D_     4096
#define NH     32
#define KH     8
#define HD     128
#define SLOTS_ 4096
#define CCOLS  6144

// ---------------------------------------------------------------------------
// Scratch (device globals: allocation-free)
// ---------------------------------------------------------------------------
__device__ __half g_Q[B_ * NH * T_ * HD];        // roped+scaled Q fp16
__device__ __half g_A[B_ * T_ * NH * HD];        // attention out fp16
__device__ __half g_Xh[B_ * T_ * D_];            // x fp16
__device__ __half g_Wqkvh[48u * D_ * HD];        // [q0..q31,k0..k7,v0..v7][4096][128]
__device__ __half g_Woh[(size_t)D_ * D_];        // wo fp16 [4096][4096]

__device__ __forceinline__ uint32_t smem_u32(const void* p) {
    uint32_t a;
    asm("{ .reg .u64 t; cvta.to.shared.u64 t, %1; cvt.u32.u64 %0, t; }"
        : "=r"(a) : "l"(p));
    return a;
}
__device__ __forceinline__ void cp_async16(uint32_t saddr, const void* gaddr) {
    asm volatile("cp.async.cg.shared.global [%0], [%1], 16;"
                 :: "r"(saddr), "l"(gaddr) : "memory");
}
__device__ __forceinline__ void cp_commit() {
    asm volatile("cp.async.commit_group;" ::: "memory");
}
template <int N>
__device__ __forceinline__ void cp_wait() {
    asm volatile("cp.async.wait_group %0;" :: "n"(N) : "memory");
}

// ---------------------------------------------------------------------------
// fp32 -> fp16 convert (8 elems/thread)
// ---------------------------------------------------------------------------
__global__ void cvt_kernel(const float* __restrict__ src, __half* __restrict__ dst,
                           int n8)
{
    int i = blockIdx.x * blockDim.x + threadIdx.x;
    if (i < n8) {
        float4 a = ((const float4*)src)[2 * i];
        float4 b = ((const float4*)src)[2 * i + 1];
        __half2 h[4];
        h[0] = __floats2half2_rn(a.x, a.y);
        h[1] = __floats2half2_rn(a.z, a.w);
        h[2] = __floats2half2_rn(b.x, b.y);
        h[3] = __floats2half2_rn(b.z, b.w);
        ((uint4*)dst)[i] = *(uint4*)h;
    }
}

// ---------------------------------------------------------------------------
// fp16 GEMM core (unchanged from passing round 14): 128x128 tile, BK=16,
// 4-stage cp.async.cg ring, one barrier per chunk. C may be GLOBAL or SHARED.
// ---------------------------------------------------------------------------
#define GK       4096
#define NCH      256
#define AH_STR   24
#define BH_STR   136
#define ASTG     (128 * AH_STR)
#define BSTG     (16 * BH_STR)
#define STGH     (ASTG + BSTG)

__device__ __forceinline__ void gemm_core_v7(const __half* __restrict__ A,
                                             const __half* __restrict__ Bsrc,
                                             int bstride,
                                             float* __restrict__ C, int ldc)
{
    __shared__ __half sh[4][STGH];
    const uint32_t smem_base = smem_u32(sh);

    const int tid = threadIdx.x;
    const int wid = tid >> 5;
    const int wm  = wid >> 2;
    const int wn  = wid & 3;

    const int a_row = tid >> 1;
    const int a_c8  = (tid & 1) * 8;
    const int b_k   = tid >> 4;
    const int b_c8  = (tid & 15) * 8;
    const __half* a_ptr = A + (size_t)a_row * GK + a_c8;
    const __half* b_ptr = Bsrc + (size_t)b_k * bstride + b_c8;
    const uint32_t a_soff = (uint32_t)(a_row * AH_STR + a_c8) * 2u;
    const uint32_t b_soff = (uint32_t)(ASTG + b_k * BH_STR + b_c8) * 2u;
    const size_t b_step16 = (size_t)16 * bstride;

    wmma::fragment<wmma::accumulator, 16, 16, 16, float> cf[4][2];
#pragma unroll
    for (int i = 0; i < 4; i++)
#pragma unroll
        for (int j = 0; j < 2; j++)
            wmma::fill_fragment(cf[i][j], 0.0f);

    auto issue = [&](int s, int ch) {
        const uint32_t sb = smem_base + (uint32_t)s * (STGH * 2u);
        cp_async16(sb + a_soff, a_ptr + ch * 16);
        cp_async16(sb + b_soff, b_ptr + (size_t)ch * b_step16);
    };

    issue(0, 0); cp_commit();
    issue(1, 1); cp_commit();
    issue(2, 2); cp_commit();

    for (int ch = 0; ch < NCH; ch++) {
        cp_wait<2>();
        __syncthreads();

        if (ch + 3 < NCH) issue((ch + 3) & 3, ch + 3);
        cp_commit();

        const __half* as = &sh[ch & 3][wm * 64 * AH_STR];
        const __half* bs = &sh[ch & 3][ASTG + wn * 32];
        wmma::fragment<wmma::matrix_a, 16, 16, 16, __half, wmma::row_major> af[4];
        wmma::fragment<wmma::matrix_b, 16, 16, 16, __half, wmma::row_major> bf[2];
#pragma unroll
        for (int i = 0; i < 4; i++)
            wmma::load_matrix_sync(af[i], as + (i * 16) * AH_STR, AH_STR);
#pragma unroll
        for (int j = 0; j < 2; j++)
            wmma::load_matrix_sync(bf[j], bs + j * 16, BH_STR);
#pragma unroll
        for (int i = 0; i < 4; i++)
#pragma unroll
            for (int j = 0; j < 2; j++)
                wmma::mma_sync(cf[i][j], af[i], bf[j], cf[i][j]);
    }

    __syncthreads();

#pragma unroll
    for (int i = 0; i < 4; i++) {
        const int row = wm * 64 + i * 16;
#pragma unroll
        for (int j = 0; j < 2; j++) {
            const int col = wn * 32 + j * 16;
            wmma::store_matrix_sync(C + (size_t)row * ldc + col, cf[i][j], ldc,
                                    wmma::mem_row_major);
        }
    }
}

// ---------------------------------------------------------------------------
// QKV GEMM with FUSED RoPE + cache scatter.
// grid (16, 48): mt over flat (B*T)/128, hy = head. The CTA tile holds one
// full head (128 dims) for 128 tokens, so rotation pairs (i, i+64) are local.
// GEMM stores into a dynamic-smem C tile; epilogue applies rope and scatters:
//   hy<32  -> g_Q fp16 (scaled)     32<=hy<40 -> roped K into kc (fp32)
//   hy>=40 -> V straight into vc (fp32)
// ---------------------------------------------------------------------------
#define CSTR    132
#define QKV_DSMEM ((128 * CSTR + 64) * 4)   // C tile + invf table

__global__ void __launch_bounds__(256, 2) qkv_gemm_kernel(const int* __restrict__ positions,
                                                          const int* __restrict__ widx,
                                                          float* __restrict__ kc,
                                                          float* __restrict__ vc)
{
    extern __shared__ float cs_dyn[];          // [128][CSTR] fp32 + invf[64]
    float* invf = cs_dyn + 128 * CSTR;

    const int mt = blockIdx.x, hy = blockIdx.y;
    const int tid = threadIdx.x;

    // inv-freq table (identical math to the old rope kernel)
    if (tid < 64)
        invf[tid] = powf(500000.0f, -(float)tid / 64.0f);

    const __half* A = g_Xh + (size_t)mt * 128 * GK;
    const __half* Bsrc = g_Wqkvh + (size_t)hy * (GK * HD);
    gemm_core_v7(A, Bsrc, HD, cs_dyn, CSTR);   // ends with stores, no final sync
    __syncthreads();                           // C tile + invf visible

    // Scatter: 2 threads per row; thread covers i = off*32 .. off*32+31
    const int r   = tid >> 1;
    const int off = tid & 1;
    const int bt  = mt * 128 + r;
    const int b   = bt >> 10, t = bt & 1023;
    const float* crow = cs_dyn + r * CSTR;

    if (hy < 32) {
        const float pos = (float)positions[bt];
        const float qscale = 0.08838834764831845f;
        __half* qo = g_Q + (((size_t)(b * NH + hy)) * T_ + t) * HD;
#pragma unroll
        for (int c = 0; c < 32; c += 2) {
            const int i = off * 32 + c;
            float a0 = pos * invf[i],     a1 = pos * invf[i + 1];
            float c0 = cosf(a0), s0 = sinf(a0);
            float c1 = cosf(a1), s1 = sinf(a1);
            float x10 = crow[i],      x11 = crow[i + 1];
            float x20 = crow[i + 64], x21 = crow[i + 65];
            *(__half2*)(qo + i) = __floats2half2_rn((x10 * c0 - x20 * s0) * qscale,
                                                    (x11 * c1 - x21 * s1) * qscale);
            *(__half2*)(qo + 64 + i) = __floats2half2_rn((x20 * c0 + x10 * s0) * qscale,
                                                         (x21 * c1 + x11 * s1) * qscale);
        }
    } else if (hy < 40) {
        const float pos = (float)positions[bt];
        const int slot = widx[bt];
        float* ko = kc + ((size_t)(hy - 32) * SLOTS_ + slot) * HD;
#pragma unroll
        for (int c = 0; c < 32; c += 2) {
            const int i = off * 32 + c;
            float a0 = pos * invf[i],     a1 = pos * invf[i + 1];
            float c0 = cosf(a0), s0 = sinf(a0);
            float c1 = cosf(a1), s1 = sinf(a1);
            float x10 = crow[i],      x11 = crow[i + 1];
            float x20 = crow[i + 64], x21 = crow[i + 65];
            *(float2*)(ko + i)      = make_float2(x10 * c0 - x20 * s0, x11 * c1 - x21 * s1);
            *(float2*)(ko + 64 + i) = make_float2(x20 * c0 + x10 * s0, x21 * c1 + x11 * s1);
        }
    } else {
        const int slot = widx[bt];
        float* vo = vc + ((size_t)(hy - 40) * SLOTS_ + slot) * HD;
#pragma unroll
        for (int c = 0; c < 32; c += 4) {
            const int i = off * 32 + c;
            *(float4*)(vo + i)      = *(const float4*)(crow + i);
            *(float4*)(vo + 64 + i) = *(const float4*)(crow + i + 64);
        }
    }
}

__global__ void __launch_bounds__(256, 2) proj_gemm_kernel(float* __restrict__ outo)
{
    const int mt = blockIdx.x, nt = blockIdx.y;
    const __half* A = g_A + (size_t)mt * 128 * (NH * HD);
    const __half* Bsrc = g_Woh + nt * 128;
    float* C = outo + (size_t)mt * 128 * D_ + nt * 128;
    gemm_core_v7(A, Bsrc, D_, C, D_);
}

// ---------------------------------------------------------------------------
// Flash attention v3 (wmma fp16, no-max softmax) — unchanged from round 14
// ---------------------------------------------------------------------------
#define KSTRH  136
#define SSTR2  68
#define PSTRH  72
#define OSTR2  132
#define QH_OFF   0
#define KH_OFF   34816
#define VH_OFF   (KH_OFF + 17408)
#define SS_OFF   (VH_OFF + 17408)
#define PH_OFF   (SS_OFF + 34816)
#define LS_OFF   (PH_OFF + 18432)
#define OS_OFF   KH_OFF
#define ATT_SMEM_BYTES (LS_OFF + 512)

__global__ void __launch_bounds__(256) attn_kernel(const float* __restrict__ kc,
                                                   const float* __restrict__ vc)
{
    extern __shared__ char smc[];
    __half* Qh  = (__half*)(smc + QH_OFF);
    __half* Kh  = (__half*)(smc + KH_OFF);
    __half* Vh  = (__half*)(smc + VH_OFF);
    float*  Ssm = (float*) (smc + SS_OFF);
    __half* Ph  = (__half*)(smc + PH_OFF);
    float*  lS  = (float*) (smc + LS_OFF);
    float*  Osm = (float*) (smc + OS_OFF);

    const int mt = blockIdx.x;
    const int n  = blockIdx.y;
    const int b  = blockIdx.z;
    const int kk = n >> 2;
    const int tid = threadIdx.x;
    const int wid = tid >> 5;
    const int m0 = mt * 128;

    const __half* qbase = g_Q + (((size_t)(b * NH + n)) * T_ + m0) * HD;
    for (int f = tid; f < 128 * 16; f += 256) {
        int r = f >> 4, c8 = (f & 15) * 8;
        *(uint4*)(Qh + r * KSTRH + c8) = *(const uint4*)(qbase + r * HD + c8);
    }
    if (tid < 128) lS[tid] = 0.f;

    const int wmp = wid >> 1, wnp = wid & 1;
    wmma::fragment<wmma::accumulator, 16, 16, 16, float> of[2][4];
#pragma unroll
    for (int i = 0; i < 2; i++)
#pragma unroll
        for (int j = 0; j < 4; j++)
            wmma::fill_fragment(of[i][j], 0.0f);

    const int wms = wid >> 1, wns = wid & 1;

    const float* kbase0 = kc + ((size_t)kk * SLOTS_ + (size_t)b * T_) * HD;
    const float* vbase0 = vc + ((size_t)kk * SLOTS_ + (size_t)b * T_) * HD;

    const int exp_row = tid >> 1, exp_off = tid & 1;

    const int ntiles = 2 * mt + 2;
    for (int jt = 0; jt < ntiles; jt++) {
        const int s0 = jt * 64;
        __syncthreads();

        {
            const float* kb = kbase0 + (size_t)s0 * HD;
            const float* vb = vbase0 + (size_t)s0 * HD;
            for (int f = tid; f < 64 * 32; f += 256) {
                int r = f >> 5, c4 = (f & 31) << 2;
                float4 kv = *(const float4*)(kb + r * HD + c4);
                __half2* kd = (__half2*)(Kh + r * KSTRH + c4);
                kd[0] = __floats2half2_rn(kv.x, kv.y);
                kd[1] = __floats2half2_rn(kv.z, kv.w);
                float4 vv = *(const float4*)(vb + r * HD + c4);
                __half2* vd = (__half2*)(Vh + r * KSTRH + c4);
                vd[0] = __floats2half2_rn(vv.x, vv.y);
                vd[1] = __floats2half2_rn(vv.z, vv.w);
            }
        }
        __syncthreads();

        {
            wmma::fragment<wmma::accumulator, 16, 16, 16, float> sf[2][2];
#pragma unroll
            for (int i = 0; i < 2; i++)
#pragma unroll
                for (int j = 0; j < 2; j++)
                    wmma::fill_fragment(sf[i][j], 0.0f);

#pragma unroll
            for (int k8 = 0; k8 < 8; k8++) {
                wmma::fragment<wmma::matrix_a, 16, 16, 16, __half, wmma::row_major> qa[2];
                wmma::fragment<wmma::matrix_b, 16, 16, 16, __half, wmma::col_major> kbf[2];
#pragma unroll
                for (int i = 0; i < 2; i++)
                    wmma::load_matrix_sync(qa[i],
                        Qh + (wms * 32 + i * 16) * KSTRH + k8 * 16, KSTRH);
#pragma unroll
                for (int j = 0; j < 2; j++)
                    wmma::load_matrix_sync(kbf[j],
                        Kh + (wns * 32 + j * 16) * KSTRH + k8 * 16, KSTRH);
#pragma unroll
                for (int i = 0; i < 2; i++)
#pragma unroll
                    for (int j = 0; j < 2; j++)
                        wmma::mma_sync(sf[i][j], qa[i], kbf[j], sf[i][j]);
            }
#pragma unroll
            for (int i = 0; i < 2; i++)
#pragma unroll
                for (int j = 0; j < 2; j++)
                    wmma::store_matrix_sync(
                        Ssm + (wms * 32 + i * 16) * SSTR2 + wns * 32 + j * 16,
                        sf[i][j], SSTR2, wmma::mem_row_major);
        }
        __syncthreads();

        {
            const int rel = s0 - m0;
            const float* srow = Ssm + exp_row * SSTR2 + exp_off * 32;
            __half* prow = Ph + exp_row * PSTRH + exp_off * 32;
            float lpart = 0.f;
#pragma unroll
            for (int c = 0; c < 32; c += 2) {
                int cg0 = exp_off * 32 + c;
                float p0 = (cg0 + rel > exp_row) ? 0.f : __expf(srow[c]);
                float p1 = (cg0 + 1 + rel > exp_row) ? 0.f : __expf(srow[c + 1]);
                lpart += p0 + p1;
                *(__half2*)(prow + c) = __floats2half2_rn(p0, p1);
            }
            lpart += __shfl_xor_sync(0xFFFFFFFF, lpart, 1);
            if (exp_off == 0) lS[exp_row] += lpart;
        }
        __syncthreads();

        {
#pragma unroll
            for (int k4 = 0; k4 < 4; k4++) {
                wmma::fragment<wmma::matrix_a, 16, 16, 16, __half, wmma::row_major> pa[2];
                wmma::fragment<wmma::matrix_b, 16, 16, 16, __half, wmma::row_major> vbf[4];
#pragma unroll
                for (int i = 0; i < 2; i++)
                    wmma::load_matrix_sync(pa[i],
                        Ph + (wmp * 32 + i * 16) * PSTRH + k4 * 16, PSTRH);
#pragma unroll
                for (int j = 0; j < 4; j++)
                    wmma::load_matrix_sync(vbf[j],
                        Vh + (k4 * 16) * KSTRH + wnp * 64 + j * 16, KSTRH);
#pragma unroll
                for (int i = 0; i < 2; i++)
#pragma unroll
                    for (int j = 0; j < 4; j++)
                        wmma::mma_sync(of[i][j], pa[i], vbf[j], of[i][j]);
            }
        }
    }

    __syncthreads();
#pragma unroll
    for (int i = 0; i < 2; i++)
#pragma unroll
        for (int j = 0; j < 4; j++)
            wmma::store_matrix_sync(
                Osm + (wmp * 32 + i * 16) * OSTR2 + wnp * 64 + j * 16,
                of[i][j], OSTR2, wmma::mem_row_major);
    __syncthreads();

    {
        const float linv = 1.0f / lS[exp_row];
        const float* orow = Osm + exp_row * OSTR2 + exp_off * 64;
        __half* ao = g_A + (((size_t)b * T_ + m0 + exp_row) * NH + n) * HD + exp_off * 64;
#pragma unroll
        for (int c = 0; c < 64; c += 4) {
            float4 v = *(const float4*)(orow + c);
            __half2 h0 = __floats2half2_rn(v.x * linv, v.y * linv);
            __half2 h1 = __floats2half2_rn(v.z * linv, v.w * linv);
            __half2* dst = (__half2*)(ao + c);
            dst[0] = h0; dst[1] = h1;
        }
    }
}

// ---------------------------------------------------------------------------
extern "C" void kernel_launch(void* const* d_in, const int* in_sizes, int n_in,
                              void* d_out, int out_size)
{
    const float* x         = (const float*)d_in[0];
    const int*   positions = (const int*)  d_in[1];
    const float* wq        = (const float*)d_in[2];
    const float* wk        = (const float*)d_in[3];
    const float* wv        = (const float*)d_in[4];
    const float* wo        = (const float*)d_in[5];
    const float* kc_in     = (const float*)d_in[6];
    const float* vc_in     = (const float*)d_in[7];
    const int*   widx      = (const int*)  d_in[8];

    float* out = (float*)d_out;
    const size_t cache_elems = (size_t)KH * SLOTS_ * HD;
    float* kc = out;
    float* vc = out + cache_elems;
    float* oo = out + 2 * cache_elems;

    cudaMemcpyAsync(kc, kc_in, cache_elems * sizeof(float), cudaMemcpyDeviceToDevice);
    cudaMemcpyAsync(vc, vc_in, cache_elems * sizeof(float), cudaMemcpyDeviceToDevice);

    static int smem_set = 0;
    if (!smem_set) {
        cudaFuncSetAttribute(attn_kernel, cudaFuncAttributeMaxDynamicSharedMemorySize,
                             ATT_SMEM_BYTES);
        cudaFuncSetAttribute(qkv_gemm_kernel, cudaFuncAttributeMaxDynamicSharedMemorySize,
                             QKV_DSMEM);
        smem_set = 1;
    }

    // 0. fp32 -> fp16 operand copies
    {
        __half* d_xh; cudaGetSymbolAddress((void**)&d_xh, g_Xh);
        __half* d_wh; cudaGetSymbolAddress((void**)&d_wh, g_Wqkvh);
        __half* d_oh; cudaGetSymbolAddress((void**)&d_oh, g_Woh);
        const int nx = B_ * T_ * D_ / 8;
        const int nq = NH * D_ * HD / 8;
        const int nk = KH * D_ * HD / 8;
        const int no = D_ * D_ / 8;
        cvt_kernel<<<(nx + 255) / 256, 256>>>(x,  d_xh, nx);
        cvt_kernel<<<(nq + 255) / 256, 256>>>(wq, d_wh, nq);
        cvt_kernel<<<(nk + 255) / 256, 256>>>(wk, d_wh + (size_t)32 * D_ * HD, nk);
        cvt_kernel<<<(nk + 255) / 256, 256>>>(wv, d_wh + (size_t)40 * D_ * HD, nk);
        cvt_kernel<<<(no + 255) / 256, 256>>>(wo, d_oh, no);
    }

    // 1. QKV projection with fused RoPE + cache scatter
    qkv_gemm_kernel<<<dim3(16, 48), 256, QKV_DSMEM>>>(positions, widx, kc, vc);

    // 2. Causal flash attention (wmma fp16, no-max softmax)
    attn_kernel<<<dim3(T_ / 128, NH, B_), 256, ATT_SMEM_BYTES>>>(kc, vc);

    // 3. Output projection
    proj_gemm_kernel<<<dim3(16, 32), 256>>>(oo);
}